// round 3
// baseline (speedup 1.0000x reference)
#include <cuda_runtime.h>
#include <math.h>

// ---------------------------------------------------------------------------
// PatchEmbed: polar bilinear sampling + two non-overlapping strided convs.
//   sampled (32,3,400,1024) -> conv1 (5,4)/(5,4) -> (32,96,80,256)
//                            -> conv2 (5,4)/(5,4) -> (32,96,16,64)
//   output: t transposed to (32,1024,96) then theta_max (32,) = pi/2
// ---------------------------------------------------------------------------

#define B_SZ   32
#define EMB    96
#define NR     400
#define NA     1024
#define H1     80
#define W1     256
#define H2     16
#define W2q    64

static __device__ float g_out1[(size_t)B_SZ * EMB * H1 * W1];     // 252 MB scratch
static __device__ float g_w2t[EMB * EMB * 5 * 4];                 // w2 transposed [o1][kr][o2][ka]

// --- transpose w2 (96,96,5,4) [o2][o1][kr][ka] -> [o1][kr][o2][ka] for coalesced tiles
__global__ void k_prep_w2(const float* __restrict__ w2) {
    int idx = blockIdx.x * 256 + threadIdx.x;
    if (idx >= EMB * EMB * 5 * 4) return;
    int ka = idx & 3;
    int t  = idx >> 2;         // (o1*5+kr)*96 + o2
    int o2 = t % 96;
    int t2 = t / 96;           // o1*5+kr
    int kr = t2 % 5;
    int o1 = t2 / 5;
    g_w2t[idx] = w2[((o2 * 96 + o1) * 5 + kr) * 4 + ka];
}

// --- fused: polar grid + bilinear sample (5-row strip) + conv1 patch GEMM
// block = (i in 0..79, b in 0..31), 256 threads. Each thread owns one output col j.
__global__ void __launch_bounds__(256) k_sample_conv1(
    const float* __restrict__ x, const float* __restrict__ dist,
    const float* __restrict__ w1, const float* __restrict__ b1) {
    extern __shared__ float sm[];
    float* s_img = sm;                 // 3*5*1024 = 15360 floats
    float* s_w   = sm + 15360;         // 60*96    = 5760  (layout [k][o])
    float* s_b   = s_w + 5760;         // 96
    float* s_cos = s_b + 96;           // 1024
    float* s_sin = s_cos + 1024;       // 1024

    const int b   = blockIdx.y;
    const int i   = blockIdx.x;        // conv1 output row
    const int tid = threadIdx.x;
    const float PI = 3.14159265358979323846f;

    // stage w1 transposed: s_w[k*96+o] = w1[o*60+k]
    for (int idx = tid; idx < 5760; idx += 256) {
        int k = idx / 96, o = idx - k * 96;
        s_w[idx] = w1[o * 60 + k];
    }
    if (tid < 96) s_b[tid] = b1[tid];

    // azimuth sin/cos tables
    for (int ia = tid; ia < NA; ia += 256) {
        float phi = 2.0f * PI * (ia + 0.5f) * (1.0f / (float)NA);
        float sv, cv;
        sincosf(phi, &sv, &cv);
        s_cos[ia] = cv;
        s_sin[ia] = sv;
    }

    // radius polynomial for the 5 rows this block covers
    const float c0 = 0.2f + dist[b * 4 + 0];
    const float c1 = 0.2f + dist[b * 4 + 1];
    const float c2 = 0.2f + dist[b * 4 + 2];
    const float c3 = 0.2f + dist[b * 4 + 3];
    const float tmax = PI * 0.5f;
    const float tm2  = tmax * tmax;
    const float ptm  = tmax * (c0 + tm2 * (c1 + tm2 * (c2 + tm2 * c3)));
    float rrow[5];
#pragma unroll
    for (int rr = 0; rr < 5; rr++) {
        float th = tmax * ((float)(i * 5 + rr) + 0.5f) * (1.0f / (float)NR);
        float t2 = th * th;
        float pt = th * (c0 + t2 * (c1 + t2 * (c2 + t2 * c3)));
        rrow[rr] = pt / ptm * 112.0f;
    }
    __syncthreads();

    // bilinear sample 5x1024x3 strip into smem
    const float* xb = x + (size_t)b * (3 * 224 * 224);
    for (int idx = tid; idx < 5 * NA; idx += 256) {
        int rr = idx >> 10;
        int ia = idx & 1023;
        float r  = rrow[rr];
        float xc = r * s_cos[ia];
        float yc = r * s_sin[ia];
        // grid[...,0] = yc/112 (width), grid[...,1] = xc/112 (height); align_corners
        float gx = (yc / 112.0f + 1.0f) * 0.5f * 223.0f;
        float gy = (xc / 112.0f + 1.0f) * 0.5f * 223.0f;
        float fx0 = floorf(gx), fy0 = floorf(gy);
        float wx1 = gx - fx0, wx0 = 1.0f - wx1;
        float wy1 = gy - fy0, wy0 = 1.0f - wy1;
        int ix0 = (int)fx0, iy0 = (int)fy0;
        int ix1 = ix0 + 1,  iy1 = iy0 + 1;
        float vx0 = (ix0 >= 0 && ix0 <= 223) ? 1.f : 0.f;
        float vx1 = (ix1 >= 0 && ix1 <= 223) ? 1.f : 0.f;
        float vy0 = (iy0 >= 0 && iy0 <= 223) ? 1.f : 0.f;
        float vy1 = (iy1 >= 0 && iy1 <= 223) ? 1.f : 0.f;
        int cx0 = min(max(ix0, 0), 223), cx1 = min(max(ix1, 0), 223);
        int cy0 = min(max(iy0, 0), 223), cy1 = min(max(iy1, 0), 223);
        float w00 = wx0 * wy0 * vx0 * vy0;
        float w10 = wx1 * wy0 * vx1 * vy0;
        float w01 = wx0 * wy1 * vx0 * vy1;
        float w11 = wx1 * wy1 * vx1 * vy1;
        int i00 = cy0 * 224 + cx0, i10 = cy0 * 224 + cx1;
        int i01 = cy1 * 224 + cx0, i11 = cy1 * 224 + cx1;
#pragma unroll
        for (int cch = 0; cch < 3; cch++) {
            const float* p = xb + cch * (224 * 224);
            float v = w00 * p[i00] + w10 * p[i10] + w01 * p[i01] + w11 * p[i11];
            s_img[(cch * 5 + rr) * NA + ia] = v;
        }
    }
    __syncthreads();

    // conv1: each thread owns output column j; 4 passes of 24 output channels
    const int j = tid;
#pragma unroll 1
    for (int pass = 0; pass < 4; pass++) {
        float acc[24];
#pragma unroll
        for (int m = 0; m < 24; m++) acc[m] = s_b[pass * 24 + m];
#pragma unroll
        for (int cc = 0; cc < 3; cc++) {
#pragma unroll
            for (int rr = 0; rr < 5; rr++) {
                float4 p4 = *(const float4*)&s_img[(cc * 5 + rr) * NA + j * 4];
                const float* pv = (const float*)&p4;
                int kb = cc * 20 + rr * 4;
#pragma unroll
                for (int ka = 0; ka < 4; ka++) {
                    const float4* wp = (const float4*)&s_w[(kb + ka) * 96 + pass * 24];
                    float pk = pv[ka];
#pragma unroll
                    for (int m4 = 0; m4 < 6; m4++) {
                        float4 w4 = wp[m4];
                        acc[m4 * 4 + 0] += pk * w4.x;
                        acc[m4 * 4 + 1] += pk * w4.y;
                        acc[m4 * 4 + 2] += pk * w4.z;
                        acc[m4 * 4 + 3] += pk * w4.w;
                    }
                }
            }
        }
        float* dst = g_out1 + (((size_t)b * EMB + pass * 24) * H1 + i) * W1 + j;
#pragma unroll
        for (int m = 0; m < 24; m++) dst[(size_t)m * H1 * W1] = acc[m];
    }
}

// --- conv2 as tiled GEMM: block = (i2 in 0..15, b), M-tile = 64 cols, N = 96, K = 1920
__global__ void __launch_bounds__(256) k_conv2(
    const float* __restrict__ b2, float* __restrict__ out) {
    extern __shared__ float sm[];
    float* s_p = sm;            // 8*5*256 = 10240 floats
    float* s_w = sm + 10240;    // 8*5*96*4 = 15360 floats
    const int b   = blockIdx.y;
    const int i2  = blockIdx.x;
    const int tid = threadIdx.x;
    const int j2  = tid & 63;
    const int g   = tid >> 6;   // 0..3 -> 24 output channels each

    float acc[24];
#pragma unroll
    for (int m = 0; m < 24; m++) acc[m] = b2[g * 24 + m];

    for (int oc = 0; oc < 96; oc += 8) {
        __syncthreads();
        // patch tile: out1[b][oc..oc+7][i2*5..i2*5+4][0..255]
        for (int f4 = tid; f4 < 2560; f4 += 256) {
            int c4 = f4 & 63;
            int t  = f4 >> 6;       // o1l*5+kr
            int kr  = t % 5;
            int o1l = t / 5;
            float4 v = *(const float4*)&g_out1[
                (((size_t)b * EMB + oc + o1l) * H1 + i2 * 5 + kr) * W1 + c4 * 4];
            ((float4*)s_p)[f4] = v;
        }
        // weight tile: contiguous slab of g_w2t
        {
            const float4* src = (const float4*)(g_w2t + oc * 5 * 96 * 4);
            for (int f4 = tid; f4 < 3840; f4 += 256)
                ((float4*)s_w)[f4] = src[f4];
        }
        __syncthreads();
#pragma unroll
        for (int o1l = 0; o1l < 8; o1l++) {
#pragma unroll
            for (int kr = 0; kr < 5; kr++) {
                float4 p = *(const float4*)&s_p[(o1l * 5 + kr) * 256 + j2 * 4];
                const float4* wrow = (const float4*)&s_w[((o1l * 5 + kr) * 96 + g * 24) * 4];
#pragma unroll
                for (int m = 0; m < 24; m++) {
                    float4 w4 = wrow[m];
                    acc[m] += p.x * w4.x + p.y * w4.y + p.z * w4.z + p.w * w4.w;
                }
            }
        }
    }
    // write transposed output t[b][i2*64+j2][o2]
    float* dst = out + (((size_t)b * 1024) + i2 * 64 + j2) * 96 + g * 24;
#pragma unroll
    for (int m4 = 0; m4 < 6; m4++) {
        float4 v;
        v.x = acc[m4 * 4 + 0];
        v.y = acc[m4 * 4 + 1];
        v.z = acc[m4 * 4 + 2];
        v.w = acc[m4 * 4 + 3];
        *(float4*)&dst[m4 * 4] = v;
    }
}

__global__ void k_theta(float* __restrict__ out) {
    if (threadIdx.x < B_SZ)
        out[(size_t)B_SZ * 1024 * EMB + threadIdx.x] = 1.57079632679489662f;
}

extern "C" void kernel_launch(void* const* d_in, const int* in_sizes, int n_in,
                              void* d_out, int out_size) {
    const float* x    = (const float*)d_in[0];
    const float* dist = (const float*)d_in[1];
    const float* w1   = (const float*)d_in[2];
    const float* b1   = (const float*)d_in[3];
    const float* w2   = (const float*)d_in[4];
    const float* b2   = (const float*)d_in[5];
    float* out = (float*)d_out;

    const int sm1 = (15360 + 5760 + 96 + 2048) * 4;   // 93056 B
    const int sm2 = (10240 + 15360) * 4;              // 102400 B
    cudaFuncSetAttribute(k_sample_conv1, cudaFuncAttributeMaxDynamicSharedMemorySize, sm1);
    cudaFuncSetAttribute(k_conv2,        cudaFuncAttributeMaxDynamicSharedMemorySize, sm2);

    k_prep_w2<<<(EMB * EMB * 5 * 4 + 255) / 256, 256>>>(w2);
    k_sample_conv1<<<dim3(H1, B_SZ), 256, sm1>>>(x, dist, w1, b1);
    k_conv2<<<dim3(H2, B_SZ), 256, sm2>>>(b2, out);
    if (out_size >= B_SZ * 1024 * EMB + B_SZ)
        k_theta<<<1, 32>>>(out);
}

// round 6
// speedup vs baseline: 2.4052x; 2.4052x over previous
#include <cuda_runtime.h>
#include <cuda_bf16.h>
#include <math.h>
#include <stdint.h>

// ---------------------------------------------------------------------------
// PatchEmbed via mma.sync bf16 hi/lo GEMMs (tcgen05 unavailable: harness
// compiles for plain compute_103, which rejects arch-specific tcgen05).
//   k_sample -> A1 [655360][64]  fp32 conv1 patch rows (k1=c*20+r*4+a, pad 60..63)
//               m1 = ((b*16+i2)*64+j2)*20 + kr*4+ka
//   GEMM1    -> A2 [32768][1920] fp32 conv2 patch rows (k2' = (kr*4+ka)*96+o1)
//   GEMM2    -> out[b][i2*64+j2][o2]  (exactly the required transposed output)
// Precision: fp32 -> bf16 hi + lo at smem staging; D = Ah*Bh + Ah*Bl + Al*Bh.
// ---------------------------------------------------------------------------

#define B_SZ 32
#define EMB  96
#define NA   1024

static __device__ float g_A1[(size_t)655360 * 64];     // 167.8 MB
static __device__ float g_A2[(size_t)32768 * 1920];    // 251.7 MB
static __device__ float g_B1[96 * 64];
static __device__ float g_B2[96 * 1920];

__device__ __forceinline__ uint32_t pack_bf2(__nv_bfloat16 a, __nv_bfloat16 b) {
    return (uint32_t)__bfloat16_as_ushort(a) | ((uint32_t)__bfloat16_as_ushort(b) << 16);
}
__device__ __forceinline__ void split_hl(float v, __nv_bfloat16& h, __nv_bfloat16& l) {
    h = __float2bfloat16(v);
    l = __float2bfloat16(v - __bfloat162float(h));
}
__device__ __forceinline__ void split_store4(float4 f, __nv_bfloat16* hp, __nv_bfloat16* lp) {
    __nv_bfloat16 h0, l0, h1, l1, h2, l2, h3, l3;
    split_hl(f.x, h0, l0); split_hl(f.y, h1, l1);
    split_hl(f.z, h2, l2); split_hl(f.w, h3, l3);
    *(uint2*)hp = make_uint2(pack_bf2(h0, h1), pack_bf2(h2, h3));
    *(uint2*)lp = make_uint2(pack_bf2(l0, l1), pack_bf2(l2, l3));
}

#define MMA_BF16(c, a0, a1, a2, a3, b0, b1) \
    asm volatile("mma.sync.aligned.m16n8k16.row.col.f32.bf16.bf16.f32 " \
                 "{%0,%1,%2,%3}, {%4,%5,%6,%7}, {%8,%9}, {%0,%1,%2,%3};" \
                 : "+f"((c)[0]), "+f"((c)[1]), "+f"((c)[2]), "+f"((c)[3]) \
                 : "r"(a0), "r"(a1), "r"(a2), "r"(a3), "r"(b0), "r"(b1))

// ---------------- prep: reorder weights to fp32 GEMM-B layouts ----------------
__global__ void k_prep(const float* __restrict__ w1, const float* __restrict__ w2) {
    int idx = blockIdx.x * 256 + threadIdx.x;
    if (idx < 96 * 64) {
        int o = idx >> 6, k = idx & 63;
        g_B1[idx] = (k < 60) ? w1[o * 60 + k] : 0.0f;
        return;
    }
    idx -= 96 * 64;
    if (idx < 96 * 1920) {
        int o2 = idx / 1920, k2 = idx - o2 * 1920;
        int o1 = k2 % 96, krka = k2 / 96;
        int kr = krka >> 2, ka = krka & 3;
        g_B2[idx] = w2[((o2 * 96 + o1) * 5 + kr) * 4 + ka];
    }
}

// ---------------- sampling: polar bilinear -> A1 patch rows (fp32) ----------
__global__ void __launch_bounds__(256) k_sample(
    const float* __restrict__ x, const float* __restrict__ dist) {
    extern __shared__ float sm[];
    float* s_img = sm;              // 3*5*1024
    float* s_cos = sm + 15360;      // 1024
    float* s_sin = s_cos + 1024;    // 1024

    const int b = blockIdx.y;
    const int i1 = blockIdx.x;      // conv1 output row 0..79
    const int tid = threadIdx.x;
    const float PI = 3.14159265358979323846f;

    for (int ia = tid; ia < NA; ia += 256) {
        float phi = 2.0f * PI * (ia + 0.5f) * (1.0f / (float)NA);
        float sv, cv; sincosf(phi, &sv, &cv);
        s_cos[ia] = cv; s_sin[ia] = sv;
    }
    const float c0 = 0.2f + dist[b * 4 + 0];
    const float c1 = 0.2f + dist[b * 4 + 1];
    const float c2 = 0.2f + dist[b * 4 + 2];
    const float c3 = 0.2f + dist[b * 4 + 3];
    const float tmax = PI * 0.5f, tm2 = tmax * tmax;
    const float ptm = tmax * (c0 + tm2 * (c1 + tm2 * (c2 + tm2 * c3)));
    float rrow[5];
#pragma unroll
    for (int rr = 0; rr < 5; rr++) {
        float th = tmax * ((float)(i1 * 5 + rr) + 0.5f) * (1.0f / 400.0f);
        float t2 = th * th;
        float pt = th * (c0 + t2 * (c1 + t2 * (c2 + t2 * c3)));
        rrow[rr] = pt / ptm * 112.0f;
    }
    __syncthreads();

    const float* xb = x + (size_t)b * (3 * 224 * 224);
    for (int idx = tid; idx < 5 * NA; idx += 256) {
        int rr = idx >> 10, ia = idx & 1023;
        float r = rrow[rr];
        float xc = r * s_cos[ia], yc = r * s_sin[ia];
        float gx = (yc / 112.0f + 1.0f) * 0.5f * 223.0f;
        float gy = (xc / 112.0f + 1.0f) * 0.5f * 223.0f;
        float fx0 = floorf(gx), fy0 = floorf(gy);
        float wx1 = gx - fx0, wx0 = 1.0f - wx1;
        float wy1 = gy - fy0, wy0 = 1.0f - wy1;
        int ix0 = (int)fx0, iy0 = (int)fy0, ix1 = ix0 + 1, iy1 = iy0 + 1;
        float vx0 = (ix0 >= 0 && ix0 <= 223) ? 1.f : 0.f;
        float vx1 = (ix1 >= 0 && ix1 <= 223) ? 1.f : 0.f;
        float vy0 = (iy0 >= 0 && iy0 <= 223) ? 1.f : 0.f;
        float vy1 = (iy1 >= 0 && iy1 <= 223) ? 1.f : 0.f;
        int cx0 = min(max(ix0, 0), 223), cx1 = min(max(ix1, 0), 223);
        int cy0 = min(max(iy0, 0), 223), cy1 = min(max(iy1, 0), 223);
        float w00 = wx0 * wy0 * vx0 * vy0, w10 = wx1 * wy0 * vx1 * vy0;
        float w01 = wx0 * wy1 * vx0 * vy1, w11 = wx1 * wy1 * vx1 * vy1;
        int i00 = cy0 * 224 + cx0, i10 = cy0 * 224 + cx1;
        int i01 = cy1 * 224 + cx0, i11 = cy1 * 224 + cx1;
#pragma unroll
        for (int cch = 0; cch < 3; cch++) {
            const float* p = xb + cch * (224 * 224);
            s_img[(cch * 5 + rr) * NA + ia] =
                w00 * p[i00] + w10 * p[i10] + w01 * p[i01] + w11 * p[i11];
        }
    }
    __syncthreads();

    // thread tid owns conv1 pixel (i1, j1=tid); A1 row m1 with patch payload.
    const int i2 = i1 / 5, kr = i1 % 5;
    const size_t m1 = ((size_t)(b * 16 + i2) * 64 + (tid >> 2)) * 20 + kr * 4 + (tid & 3);
    float4* dst = (float4*)(g_A1 + m1 * 64);
#pragma unroll
    for (int cc = 0; cc < 3; cc++)
#pragma unroll
        for (int rr = 0; rr < 5; rr++)
            dst[cc * 5 + rr] = *(const float4*)&s_img[(cc * 5 + rr) * NA + tid * 4];
    dst[15] = make_float4(0.f, 0.f, 0.f, 0.f);
}

// ---------------- generic hi/lo mma.sync GEMM: tile M=128, N=96, K chunks 64 --
// EPI=1: write A2 (fp32, conv2 patch-row reindex) with bias.  EPI=2: write out.
static constexpr int APAD = 72;   // bf16 row stride (conflict-free LDS)
static constexpr int SM_AH = 0;
static constexpr int SM_AL = 128 * APAD;
static constexpr int SM_BH = 2 * 128 * APAD;
static constexpr int SM_BL = 2 * 128 * APAD + 96 * APAD;
static constexpr int SM_BIAS = 2 * 128 * APAD + 2 * 96 * APAD;      // bf16 units
static constexpr int SMEM_GEMM = SM_BIAS * 2 + 96 * 4;              // 64896 B

template <int EPI>
__global__ void __launch_bounds__(256) k_gemm(
    const float* __restrict__ A, const float* __restrict__ Bm,
    const float* __restrict__ bias, int K, int nchunks, float* __restrict__ outp) {
    extern __shared__ char smc[];
    __nv_bfloat16* sAh = (__nv_bfloat16*)smc + SM_AH;
    __nv_bfloat16* sAl = (__nv_bfloat16*)smc + SM_AL;
    __nv_bfloat16* sBh = (__nv_bfloat16*)smc + SM_BH;
    __nv_bfloat16* sBl = (__nv_bfloat16*)smc + SM_BL;
    float* s_bias = (float*)(smc + SM_BIAS * 2);

    const int tid = threadIdx.x, w = tid >> 5, l = tid & 31;
    if (tid < 96) s_bias[tid] = bias[tid];

    const size_t m0 = (size_t)blockIdx.x * 128;
    float acc[12][4];
#pragma unroll
    for (int nt = 0; nt < 12; nt++)
#pragma unroll
        for (int i = 0; i < 4; i++) acc[nt][i] = 0.f;

    const int lrow = tid >> 1;
    const int cb = (tid & 1) * 32;

    for (int kc = 0; kc < nchunks; kc++) {
        __syncthreads();
        {   // A tile: 128 x 64 fp32 -> hi/lo bf16
            const float4* ap = (const float4*)(A + (m0 + lrow) * (size_t)K + kc * 64 + cb);
            __nv_bfloat16* hp = sAh + lrow * APAD + cb;
            __nv_bfloat16* lp = sAl + lrow * APAD + cb;
#pragma unroll
            for (int t = 0; t < 8; t++)
                split_store4(ap[t], hp + t * 4, lp + t * 4);
        }
        if (tid < 192) {   // B tile: 96 x 64
            const int br = tid >> 1;
            const int bcb = (tid & 1) * 32;
            const float4* bp = (const float4*)(Bm + (size_t)br * K + kc * 64 + bcb);
            __nv_bfloat16* hp = sBh + br * APAD + bcb;
            __nv_bfloat16* lp = sBl + br * APAD + bcb;
#pragma unroll
            for (int t = 0; t < 8; t++)
                split_store4(bp[t], hp + t * 4, lp + t * 4);
        }
        __syncthreads();

#pragma unroll
        for (int ks = 0; ks < 4; ks++) {
            const int abase = (w * 16 + (l >> 2)) * APAD + ks * 16 + (l & 3) * 2;
            uint32_t ah0 = *(const uint32_t*)(sAh + abase);
            uint32_t ah1 = *(const uint32_t*)(sAh + abase + 8 * APAD);
            uint32_t ah2 = *(const uint32_t*)(sAh + abase + 8);
            uint32_t ah3 = *(const uint32_t*)(sAh + abase + 8 * APAD + 8);
            uint32_t al0 = *(const uint32_t*)(sAl + abase);
            uint32_t al1 = *(const uint32_t*)(sAl + abase + 8 * APAD);
            uint32_t al2 = *(const uint32_t*)(sAl + abase + 8);
            uint32_t al3 = *(const uint32_t*)(sAl + abase + 8 * APAD + 8);
#pragma unroll
            for (int nt = 0; nt < 12; nt++) {
                const int bbase = (nt * 8 + (l >> 2)) * APAD + ks * 16 + (l & 3) * 2;
                uint32_t bh0 = *(const uint32_t*)(sBh + bbase);
                uint32_t bh1 = *(const uint32_t*)(sBh + bbase + 8);
                uint32_t bl0 = *(const uint32_t*)(sBl + bbase);
                uint32_t bl1 = *(const uint32_t*)(sBl + bbase + 8);
                MMA_BF16(acc[nt], ah0, ah1, ah2, ah3, bh0, bh1);
                MMA_BF16(acc[nt], ah0, ah1, ah2, ah3, bl0, bl1);
                MMA_BF16(acc[nt], al0, al1, al2, al3, bh0, bh1);
            }
        }
    }

    // epilogue
    const int r0 = w * 16 + (l >> 2);
    const int cl = (l & 3) * 2;
#pragma unroll
    for (int half = 0; half < 2; half++) {
        const size_t m = m0 + r0 + half * 8;
        if (EPI == 2) {
            float* dst = outp + m * 96;
#pragma unroll
            for (int nt = 0; nt < 12; nt++) {
                const int c = nt * 8 + cl;
                float2 v;
                v.x = acc[nt][half * 2 + 0] + s_bias[c];
                v.y = acc[nt][half * 2 + 1] + s_bias[c + 1];
                *(float2*)(dst + c) = v;
            }
        } else {
            const size_t rowA2 = m / 20;
            const int krka = (int)(m % 20);
            float* dst = g_A2 + rowA2 * 1920 + (size_t)krka * 96;
#pragma unroll
            for (int nt = 0; nt < 12; nt++) {
                const int c = nt * 8 + cl;
                float2 v;
                v.x = acc[nt][half * 2 + 0] + s_bias[c];
                v.y = acc[nt][half * 2 + 1] + s_bias[c + 1];
                *(float2*)(dst + c) = v;
            }
        }
    }
}

__global__ void k_theta(float* __restrict__ out) {
    if (threadIdx.x < B_SZ)
        out[(size_t)B_SZ * 1024 * EMB + threadIdx.x] = 1.57079632679489662f;
}

extern "C" void kernel_launch(void* const* d_in, const int* in_sizes, int n_in,
                              void* d_out, int out_size) {
    const float* x    = (const float*)d_in[0];
    const float* dist = (const float*)d_in[1];
    const float* w1   = (const float*)d_in[2];
    const float* b1   = (const float*)d_in[3];
    const float* w2   = (const float*)d_in[4];
    const float* b2   = (const float*)d_in[5];
    float* out = (float*)d_out;

    const int sm_sample = (15360 + 2048) * 4;
    cudaFuncSetAttribute(k_sample, cudaFuncAttributeMaxDynamicSharedMemorySize, sm_sample);
    cudaFuncSetAttribute(k_gemm<1>, cudaFuncAttributeMaxDynamicSharedMemorySize, SMEM_GEMM);
    cudaFuncSetAttribute(k_gemm<2>, cudaFuncAttributeMaxDynamicSharedMemorySize, SMEM_GEMM);

    float *A1, *A2, *B1, *B2;
    cudaGetSymbolAddress((void**)&A1, g_A1);
    cudaGetSymbolAddress((void**)&A2, g_A2);
    cudaGetSymbolAddress((void**)&B1, g_B1);
    cudaGetSymbolAddress((void**)&B2, g_B2);

    k_prep<<<(96 * 64 + 96 * 1920 + 255) / 256, 256>>>(w1, w2);
    k_sample<<<dim3(80, B_SZ), 256, sm_sample>>>(x, dist);
    // GEMM1: M=655360 (5120 tiles), K=64, 1 chunk -> writes A2
    k_gemm<1><<<5120, 256, SMEM_GEMM>>>(A1, B1, b1, 64, 1, nullptr);
    // GEMM2: M=32768 (256 tiles), K=1920, 30 chunks -> writes out
    k_gemm<2><<<256, 256, SMEM_GEMM>>>(A2, B2, b2, 1920, 30, out);
    if (out_size >= B_SZ * 1024 * EMB + B_SZ)
        k_theta<<<1, 32>>>(out);
}

// round 7
// speedup vs baseline: 3.2122x; 1.3355x over previous
#include <cuda_runtime.h>
#include <cuda_bf16.h>
#include <math.h>
#include <stdint.h>

// ---------------------------------------------------------------------------
// PatchEmbed via mma.sync bf16 hi/lo GEMMs, cp.async staging + ldmatrix frags.
//   k_sample -> A1 hi/lo [655360][64] bf16 (conv1 patch rows, pad k 60..63)
//   GEMM1    -> A2 hi/lo [32768][1920] bf16 (conv2 patch rows, k2'=(kr*4+ka)*96+o1)
//   GEMM2    -> out[b][i2*64+j2][o2]  (required transposed output) + theta_max
// Precision: D = Ah*Bh + Ah*Bl + Al*Bh (fp32 accum) -> rel_err ~1e-5.
// ---------------------------------------------------------------------------

#define B_SZ 32
#define EMB  96
#define NA   1024

static __device__ __align__(256) __nv_bfloat16 g_A1h[(size_t)655360 * 64];
static __device__ __align__(256) __nv_bfloat16 g_A1l[(size_t)655360 * 64];
static __device__ __align__(256) __nv_bfloat16 g_A2h[(size_t)32768 * 1920];
static __device__ __align__(256) __nv_bfloat16 g_A2l[(size_t)32768 * 1920];
static __device__ __align__(256) __nv_bfloat16 g_B1h[96 * 64];
static __device__ __align__(256) __nv_bfloat16 g_B1l[96 * 64];
static __device__ __align__(256) __nv_bfloat16 g_B2h[96 * 1920];
static __device__ __align__(256) __nv_bfloat16 g_B2l[96 * 1920];

__device__ __forceinline__ uint32_t pack_bf2(__nv_bfloat16 a, __nv_bfloat16 b) {
    return (uint32_t)__bfloat16_as_ushort(a) | ((uint32_t)__bfloat16_as_ushort(b) << 16);
}
__device__ __forceinline__ void split_hl(float v, __nv_bfloat16& h, __nv_bfloat16& l) {
    h = __float2bfloat16(v);
    l = __float2bfloat16(v - __bfloat162float(h));
}
__device__ __forceinline__ uint32_t smem_u32(const void* p) {
    uint32_t a;
    asm("{ .reg .u64 t; cvta.to.shared.u64 t, %1; cvt.u32.u64 %0, t; }" : "=r"(a) : "l"(p));
    return a;
}
__device__ __forceinline__ void cp16(uint32_t dst, const void* src) {
    asm volatile("cp.async.cg.shared.global [%0], [%1], 16;" :: "r"(dst), "l"(src) : "memory");
}
template <int N> __device__ __forceinline__ void cp_wait() {
    asm volatile("cp.async.wait_group %0;" :: "n"(N) : "memory");
}
__device__ __forceinline__ void cp_commit() {
    asm volatile("cp.async.commit_group;" ::: "memory");
}
#define LDSM_X4(r0, r1, r2, r3, a) \
    asm volatile("ldmatrix.sync.aligned.m8n8.x4.shared.b16 {%0,%1,%2,%3}, [%4];" \
                 : "=r"(r0), "=r"(r1), "=r"(r2), "=r"(r3) : "r"(a))
#define LDSM_X2(r0, r1, a) \
    asm volatile("ldmatrix.sync.aligned.m8n8.x2.shared.b16 {%0,%1}, [%2];" \
                 : "=r"(r0), "=r"(r1) : "r"(a))
#define MMA_BF16(c, a0, a1, a2, a3, b0, b1) \
    asm volatile("mma.sync.aligned.m16n8k16.row.col.f32.bf16.bf16.f32 " \
                 "{%0,%1,%2,%3}, {%4,%5,%6,%7}, {%8,%9}, {%0,%1,%2,%3};" \
                 : "+f"((c)[0]), "+f"((c)[1]), "+f"((c)[2]), "+f"((c)[3]) \
                 : "r"(a0), "r"(a1), "r"(a2), "r"(a3), "r"(b0), "r"(b1))

// ---------------- prep: split/reorder weights to bf16 hi/lo ----------------
__global__ void k_prep(const float* __restrict__ w1, const float* __restrict__ w2) {
    int idx = blockIdx.x * 256 + threadIdx.x;
    if (idx < 96 * 64) {
        int o = idx >> 6, k = idx & 63;
        float v = (k < 60) ? w1[o * 60 + k] : 0.0f;
        __nv_bfloat16 h, l; split_hl(v, h, l);
        g_B1h[idx] = h; g_B1l[idx] = l;
        return;
    }
    idx -= 96 * 64;
    if (idx < 96 * 1920) {
        int o2 = idx / 1920, k2 = idx - o2 * 1920;
        int o1 = k2 % 96, krka = k2 / 96;
        int kr = krka >> 2, ka = krka & 3;
        float v = w2[((o2 * 96 + o1) * 5 + kr) * 4 + ka];
        __nv_bfloat16 h, l; split_hl(v, h, l);
        g_B2h[idx] = h; g_B2l[idx] = l;
    }
}

// ---------------- sampling: polar bilinear -> A1 hi/lo patch rows -----------
__global__ void __launch_bounds__(256) k_sample(
    const float* __restrict__ x, const float* __restrict__ dist) {
    extern __shared__ float sm[];
    float* s_img = sm;              // 3*5*1024
    float* s_cos = sm + 15360;      // 1024
    float* s_sin = s_cos + 1024;    // 1024

    const int b = blockIdx.y;
    const int i1 = blockIdx.x;      // conv1 output row 0..79
    const int tid = threadIdx.x;
    const float PI = 3.14159265358979323846f;

    for (int ia = tid; ia < NA; ia += 256) {
        float phi = 2.0f * PI * (ia + 0.5f) * (1.0f / (float)NA);
        float sv, cv; sincosf(phi, &sv, &cv);
        s_cos[ia] = cv; s_sin[ia] = sv;
    }
    const float c0 = 0.2f + dist[b * 4 + 0];
    const float c1 = 0.2f + dist[b * 4 + 1];
    const float c2 = 0.2f + dist[b * 4 + 2];
    const float c3 = 0.2f + dist[b * 4 + 3];
    const float tmax = PI * 0.5f, tm2 = tmax * tmax;
    const float ptm = tmax * (c0 + tm2 * (c1 + tm2 * (c2 + tm2 * c3)));
    float rrow[5];
#pragma unroll
    for (int rr = 0; rr < 5; rr++) {
        float th = tmax * ((float)(i1 * 5 + rr) + 0.5f) * (1.0f / 400.0f);
        float t2 = th * th;
        float pt = th * (c0 + t2 * (c1 + t2 * (c2 + t2 * c3)));
        rrow[rr] = pt / ptm * 112.0f;
    }
    __syncthreads();

    const float* xb = x + (size_t)b * (3 * 224 * 224);
    for (int idx = tid; idx < 5 * NA; idx += 256) {
        int rr = idx >> 10, ia = idx & 1023;
        float r = rrow[rr];
        float xc = r * s_cos[ia], yc = r * s_sin[ia];
        float gx = (yc / 112.0f + 1.0f) * 0.5f * 223.0f;
        float gy = (xc / 112.0f + 1.0f) * 0.5f * 223.0f;
        float fx0 = floorf(gx), fy0 = floorf(gy);
        float wx1 = gx - fx0, wx0 = 1.0f - wx1;
        float wy1 = gy - fy0, wy0 = 1.0f - wy1;
        int ix0 = (int)fx0, iy0 = (int)fy0, ix1 = ix0 + 1, iy1 = iy0 + 1;
        float vx0 = (ix0 >= 0 && ix0 <= 223) ? 1.f : 0.f;
        float vx1 = (ix1 >= 0 && ix1 <= 223) ? 1.f : 0.f;
        float vy0 = (iy0 >= 0 && iy0 <= 223) ? 1.f : 0.f;
        float vy1 = (iy1 >= 0 && iy1 <= 223) ? 1.f : 0.f;
        int cx0 = min(max(ix0, 0), 223), cx1 = min(max(ix1, 0), 223);
        int cy0 = min(max(iy0, 0), 223), cy1 = min(max(iy1, 0), 223);
        float w00 = wx0 * wy0 * vx0 * vy0, w10 = wx1 * wy0 * vx1 * vy0;
        float w01 = wx0 * wy1 * vx0 * vy1, w11 = wx1 * wy1 * vx1 * vy1;
        int i00 = cy0 * 224 + cx0, i10 = cy0 * 224 + cx1;
        int i01 = cy1 * 224 + cx0, i11 = cy1 * 224 + cx1;
#pragma unroll
        for (int cch = 0; cch < 3; cch++) {
            const float* p = xb + cch * (224 * 224);
            s_img[(cch * 5 + rr) * NA + ia] =
                w00 * p[i00] + w10 * p[i10] + w01 * p[i01] + w11 * p[i11];
        }
    }
    __syncthreads();

    // thread tid -> conv1 pixel (i1, j1=tid); A1 row m1, bf16 hi/lo.
    const int i2 = i1 / 5, kr = i1 % 5;
    const size_t m1 = ((size_t)(b * 16 + i2) * 64 + (tid >> 2)) * 20 + kr * 4 + (tid & 3);
    uint32_t hu[32], lu[32];
#pragma unroll
    for (int cc = 0; cc < 3; cc++) {
#pragma unroll
        for (int rr = 0; rr < 5; rr++) {
            float4 p4 = *(const float4*)&s_img[(cc * 5 + rr) * NA + tid * 4];
            int ub = cc * 10 + rr * 2;
            __nv_bfloat16 h0, l0, h1, l1, h2, l2, h3, l3;
            split_hl(p4.x, h0, l0); split_hl(p4.y, h1, l1);
            split_hl(p4.z, h2, l2); split_hl(p4.w, h3, l3);
            hu[ub] = pack_bf2(h0, h1); hu[ub + 1] = pack_bf2(h2, h3);
            lu[ub] = pack_bf2(l0, l1); lu[ub + 1] = pack_bf2(l2, l3);
        }
    }
    hu[30] = hu[31] = lu[30] = lu[31] = 0u;
    uint4* dh = (uint4*)(g_A1h + m1 * 64);
    uint4* dl = (uint4*)(g_A1l + m1 * 64);
#pragma unroll
    for (int t = 0; t < 8; t++) {
        dh[t] = *(uint4*)&hu[t * 4];
        dl[t] = *(uint4*)&lu[t * 4];
    }
}

// ---------------- GEMM: M-tile 64, N=96, K chunks 64, cp.async + ldmatrix ---
// smem per stage (bytes): Ah 64*144=9216 | Al 9216 | Bh 96*144=13824 | Bl 13824
static constexpr int STG = 46080;
static constexpr int SMEM_GEMM = 2 * STG + 512;   // + bias

__device__ __forceinline__ void stage_copy(
    uint32_t smb, int s,
    const __nv_bfloat16* __restrict__ Ah, const __nv_bfloat16* __restrict__ Al,
    const __nv_bfloat16* __restrict__ Bh, const __nv_bfloat16* __restrict__ Bl,
    size_t m0, int K, int kc, int tid) {
    const uint32_t base = smb + s * STG;
    const size_t koff = (size_t)kc * 64;
#pragma unroll
    for (int k = 0; k < 4; k++) {          // A: 1024 x 16B
        int i = tid + k * 256;
        const __nv_bfloat16* src = (i & 512) ? Al : Ah;
        int rr = (i >> 3) & 63, c = i & 7;
        cp16(base + (i >> 9) * 9216 + rr * 144 + c * 16,
             src + (m0 + rr) * (size_t)K + koff + c * 8);
    }
#pragma unroll
    for (int k = 0; k < 6; k++) {          // B: 1536 x 16B
        int i = tid + k * 256;
        int arr = (i >= 768) ? 1 : 0;
        int jj = i - arr * 768;
        const __nv_bfloat16* src = arr ? Bl : Bh;
        int rr = jj >> 3, c = jj & 7;
        cp16(base + 18432 + arr * 13824 + rr * 144 + c * 16,
             src + (size_t)rr * K + koff + c * 8);
    }
    cp_commit();
}

template <int EPI>
__global__ void __launch_bounds__(256) k_gemm(
    const __nv_bfloat16* __restrict__ Ah, const __nv_bfloat16* __restrict__ Al,
    const __nv_bfloat16* __restrict__ Bh, const __nv_bfloat16* __restrict__ Bl,
    const float* __restrict__ bias, int K, int nch, float* __restrict__ outp) {
    extern __shared__ char smc[];
    const uint32_t smb = smem_u32(smc);
    float* s_bias = (float*)(smc + 2 * STG);
    const int tid = threadIdx.x, w = tid >> 5, l = tid & 31;
    if (tid < 96) s_bias[tid] = bias[tid];

    const int warp_m = w & 1, warp_n = w >> 1;        // 2 x 4 warps
    const int mbase = warp_m * 32, nbase = warp_n * 24;
    const size_t m0 = (size_t)blockIdx.x * 64;

    // per-lane ldmatrix address components
    const int t8 = l >> 3, lr = l & 7;
    const int a_r = (t8 & 1) * 8 + lr, a_c = (t8 >> 1) * 16;
    const int b_r = (t8 >> 1) * 8 + lr, b_c = (t8 & 1) * 16;
    const int b2_r = 16 + lr, b2_c = (t8 & 1) * 16;

    float acc[2][3][4];
#pragma unroll
    for (int mf = 0; mf < 2; mf++)
#pragma unroll
        for (int nt = 0; nt < 3; nt++)
#pragma unroll
            for (int i = 0; i < 4; i++) acc[mf][nt][i] = 0.f;

    stage_copy(smb, 0, Ah, Al, Bh, Bl, m0, K, 0, tid);

    for (int kc = 0; kc < nch; kc++) {
        if (kc + 1 < nch) {
            stage_copy(smb, (kc + 1) & 1, Ah, Al, Bh, Bl, m0, K, kc + 1, tid);
            cp_wait<1>();
        } else {
            cp_wait<0>();
        }
        __syncthreads();

        const uint32_t sA = smb + (kc & 1) * STG;
        const uint32_t aAh = sA + (mbase + a_r) * 144 + a_c;
        const uint32_t aAl = aAh + 9216;
        const uint32_t sB = sA + 18432;
        const uint32_t aBh = sB + (nbase + b_r) * 144 + b_c;
        const uint32_t aBl = aBh + 13824;
        const uint32_t aBh2 = sB + (nbase + b2_r) * 144 + b2_c;
        const uint32_t aBl2 = aBh2 + 13824;

#pragma unroll
        for (int ks = 0; ks < 4; ks++) {
            const int kb = ks * 32;
            uint32_t ah[2][4], al[2][4], bh[3][2], bl[3][2];
            LDSM_X4(ah[0][0], ah[0][1], ah[0][2], ah[0][3], aAh + kb);
            LDSM_X4(ah[1][0], ah[1][1], ah[1][2], ah[1][3], aAh + 2304 + kb);
            LDSM_X4(al[0][0], al[0][1], al[0][2], al[0][3], aAl + kb);
            LDSM_X4(al[1][0], al[1][1], al[1][2], al[1][3], aAl + 2304 + kb);
            LDSM_X4(bh[0][0], bh[0][1], bh[1][0], bh[1][1], aBh + kb);
            LDSM_X2(bh[2][0], bh[2][1], aBh2 + kb);
            LDSM_X4(bl[0][0], bl[0][1], bl[1][0], bl[1][1], aBl + kb);
            LDSM_X2(bl[2][0], bl[2][1], aBl2 + kb);
#pragma unroll
            for (int mf = 0; mf < 2; mf++)
#pragma unroll
                for (int nt = 0; nt < 3; nt++) {
                    MMA_BF16(acc[mf][nt], ah[mf][0], ah[mf][1], ah[mf][2], ah[mf][3],
                             bh[nt][0], bh[nt][1]);
                    MMA_BF16(acc[mf][nt], ah[mf][0], ah[mf][1], ah[mf][2], ah[mf][3],
                             bl[nt][0], bl[nt][1]);
                    MMA_BF16(acc[mf][nt], al[mf][0], al[mf][1], al[mf][2], al[mf][3],
                             bh[nt][0], bh[nt][1]);
                }
        }
        __syncthreads();
    }

    // epilogue
#pragma unroll
    for (int mf = 0; mf < 2; mf++)
#pragma unroll
        for (int half = 0; half < 2; half++) {
            const size_t m = m0 + mbase + mf * 16 + (l >> 2) + half * 8;
            if (EPI == 2) {
                float* dst = outp + m * 96;
#pragma unroll
                for (int nt = 0; nt < 3; nt++) {
                    const int n = nbase + nt * 8 + (l & 3) * 2;
                    float2 v;
                    v.x = acc[mf][nt][half * 2 + 0] + s_bias[n];
                    v.y = acc[mf][nt][half * 2 + 1] + s_bias[n + 1];
                    *(float2*)(dst + n) = v;
                }
            } else {
                const size_t rowA2 = m / 20;
                const int krka = (int)(m % 20);
                const size_t rbase = rowA2 * 1920 + (size_t)krka * 96;
#pragma unroll
                for (int nt = 0; nt < 3; nt++) {
                    const int n = nbase + nt * 8 + (l & 3) * 2;
                    float vx = acc[mf][nt][half * 2 + 0] + s_bias[n];
                    float vy = acc[mf][nt][half * 2 + 1] + s_bias[n + 1];
                    __nv_bfloat16 hx, lx, hy, ly;
                    split_hl(vx, hx, lx); split_hl(vy, hy, ly);
                    *(uint32_t*)(g_A2h + rbase + n) = pack_bf2(hx, hy);
                    *(uint32_t*)(g_A2l + rbase + n) = pack_bf2(lx, ly);
                }
            }
        }
}

__global__ void k_theta(float* __restrict__ out) {
    if (threadIdx.x < B_SZ)
        out[(size_t)B_SZ * 1024 * EMB + threadIdx.x] = 1.57079632679489662f;
}

extern "C" void kernel_launch(void* const* d_in, const int* in_sizes, int n_in,
                              void* d_out, int out_size) {
    const float* x    = (const float*)d_in[0];
    const float* dist = (const float*)d_in[1];
    const float* w1   = (const float*)d_in[2];
    const float* b1   = (const float*)d_in[3];
    const float* w2   = (const float*)d_in[4];
    const float* b2   = (const float*)d_in[5];
    float* out = (float*)d_out;

    const int sm_sample = (15360 + 2048) * 4;
    cudaFuncSetAttribute(k_sample, cudaFuncAttributeMaxDynamicSharedMemorySize, sm_sample);
    cudaFuncSetAttribute(k_gemm<1>, cudaFuncAttributeMaxDynamicSharedMemorySize, SMEM_GEMM);
    cudaFuncSetAttribute(k_gemm<2>, cudaFuncAttributeMaxDynamicSharedMemorySize, SMEM_GEMM);

    __nv_bfloat16 *A1h, *A1l, *A2h, *A2l, *B1h, *B1l, *B2h, *B2l;
    cudaGetSymbolAddress((void**)&A1h, g_A1h);
    cudaGetSymbolAddress((void**)&A1l, g_A1l);
    cudaGetSymbolAddress((void**)&A2h, g_A2h);
    cudaGetSymbolAddress((void**)&A2l, g_A2l);
    cudaGetSymbolAddress((void**)&B1h, g_B1h);
    cudaGetSymbolAddress((void**)&B1l, g_B1l);
    cudaGetSymbolAddress((void**)&B2h, g_B2h);
    cudaGetSymbolAddress((void**)&B2l, g_B2l);

    k_prep<<<(96 * 64 + 96 * 1920 + 255) / 256, 256>>>(w1, w2);
    k_sample<<<dim3(80, B_SZ), 256, sm_sample>>>(x, dist);
    // GEMM1: M=655360 -> 10240 tiles of 64, K=64 (1 chunk) -> writes A2 hi/lo
    k_gemm<1><<<10240, 256, SMEM_GEMM>>>(A1h, A1l, B1h, B1l, b1, 64, 1, nullptr);
    // GEMM2: M=32768 -> 512 tiles of 64, K=1920 (30 chunks) -> writes out
    k_gemm<2><<<512, 256, SMEM_GEMM>>>(A2h, A2l, B2h, B2l, b2, 1920, 30, out);
    if (out_size >= B_SZ * 1024 * EMB + B_SZ)
        k_theta<<<1, 32>>>(out);
}

// round 10
// speedup vs baseline: 5.7256x; 1.7825x over previous
#include <cuda_runtime.h>
#include <cuda_bf16.h>
#include <math.h>
#include <stdint.h>

// ---------------------------------------------------------------------------
// PatchEmbed collapsed to ONE GEMM with merged conv weights.
//   conv2(conv1(s)) == s_patches[32768][1200] @ Wm[96][1200] + bm
//   (stride==kernel for both convs -> patches never overlap; linear compose)
// k-order: k = dr*48 + c*16 + da  (dr=kr*5+r5, da=ka*4+a4), pad K->1216.
// Precision: hi/lo bf16 split, D = Ah*Bh + Ah*Bl + Al*Bh (fp32 acc).
// ---------------------------------------------------------------------------

#define B_SZ 32
#define EMB  96
#define NA   1024
#define KPAD 1216

static __device__ __align__(256) __nv_bfloat16 g_Ah[(size_t)32768 * KPAD];
static __device__ __align__(256) __nv_bfloat16 g_Al[(size_t)32768 * KPAD];
static __device__ __align__(256) __nv_bfloat16 g_Bh[96 * KPAD];
static __device__ __align__(256) __nv_bfloat16 g_Bl[96 * KPAD];
static __device__ float g_bm[96];

__device__ __forceinline__ uint32_t pack_bf2(__nv_bfloat16 a, __nv_bfloat16 b) {
    return (uint32_t)__bfloat16_as_ushort(a) | ((uint32_t)__bfloat16_as_ushort(b) << 16);
}
__device__ __forceinline__ void split_hl(float v, __nv_bfloat16& h, __nv_bfloat16& l) {
    h = __float2bfloat16(v);
    l = __float2bfloat16(v - __bfloat162float(h));
}
__device__ __forceinline__ uint32_t smem_u32(const void* p) {
    uint32_t a;
    asm("{ .reg .u64 t; cvta.to.shared.u64 t, %1; cvt.u32.u64 %0, t; }" : "=r"(a) : "l"(p));
    return a;
}
__device__ __forceinline__ void cp16(uint32_t dst, const void* src) {
    asm volatile("cp.async.cg.shared.global [%0], [%1], 16;" :: "r"(dst), "l"(src) : "memory");
}
template <int N> __device__ __forceinline__ void cp_wait() {
    asm volatile("cp.async.wait_group %0;" :: "n"(N) : "memory");
}
__device__ __forceinline__ void cp_commit() {
    asm volatile("cp.async.commit_group;" ::: "memory");
}
#define LDSM_X4(r0, r1, r2, r3, a) \
    asm volatile("ldmatrix.sync.aligned.m8n8.x4.shared.b16 {%0,%1,%2,%3}, [%4];" \
                 : "=r"(r0), "=r"(r1), "=r"(r2), "=r"(r3) : "r"(a))
#define LDSM_X2(r0, r1, a) \
    asm volatile("ldmatrix.sync.aligned.m8n8.x2.shared.b16 {%0,%1}, [%2];" \
                 : "=r"(r0), "=r"(r1) : "r"(a))
#define MMA_BF16(c, a0, a1, a2, a3, b0, b1) \
    asm volatile("mma.sync.aligned.m16n8k16.row.col.f32.bf16.bf16.f32 " \
                 "{%0,%1,%2,%3}, {%4,%5,%6,%7}, {%8,%9}, {%0,%1,%2,%3};" \
                 : "+f"((c)[0]), "+f"((c)[1]), "+f"((c)[2]), "+f"((c)[3]) \
                 : "r"(a0), "r"(a1), "r"(a2), "r"(a3), "r"(b0), "r"(b1))

// ---------------- prep: merge conv weights, split hi/lo; bias; theta --------
__global__ void __launch_bounds__(256) k_prep(
    const float* __restrict__ w1, const float* __restrict__ b1,
    const float* __restrict__ w2, const float* __restrict__ b2,
    float* __restrict__ out, int write_theta) {
    __shared__ float s_w1[96 * 60];
    __shared__ float s_w2[96 * 20];
    const int o2 = blockIdx.x;
    const int tid = threadIdx.x;
    for (int i = tid; i < 96 * 60; i += 256) s_w1[i] = w1[i];
    for (int i = tid; i < 96 * 20; i += 256) s_w2[i] = w2[o2 * (96 * 20) + i];
    __syncthreads();

    for (int k = tid; k < KPAD; k += 256) {
        float acc = 0.f;
        if (k < 1200) {
            int dr = k / 48, rem = k % 48;
            int c = rem >> 4, da = rem & 15;
            int kr = dr / 5, r5 = dr % 5;
            int ka = da >> 2, a4 = da & 3;
            int w2i = kr * 4 + ka;
            int w1i = c * 20 + r5 * 4 + a4;
#pragma unroll 4
            for (int o1 = 0; o1 < 96; o1++)
                acc += s_w2[o1 * 20 + w2i] * s_w1[o1 * 60 + w1i];
        }
        __nv_bfloat16 h, l; split_hl(acc, h, l);
        g_Bh[o2 * KPAD + k] = h;
        g_Bl[o2 * KPAD + k] = l;
    }
    if (tid == 0) {
        float bm = b2[o2];
        for (int o1 = 0; o1 < 96; o1++) {
            float bv = b1[o1];
            for (int t = 0; t < 20; t++) bm += s_w2[o1 * 20 + t] * bv * ((t >= 0) ? 0.f : 0.f) + 0.f;
        }
        // (recompute cleanly)
        bm = b2[o2];
        for (int o1 = 0; o1 < 96; o1++) {
            float s = 0.f;
            for (int t = 0; t < 20; t++) s += s_w2[o1 * 20 + t];
            bm += s * b1[o1];
        }
        g_bm[o2] = bm;
    }
    if (write_theta && o2 == 0 && tid < B_SZ)
        out[(size_t)B_SZ * 1024 * EMB + tid] = 1.57079632679489662f;
}

// ---------------- sampling: polar bilinear -> A patch rows (hi/lo bf16) -----
// block g = (b, group of 5 sampled rows); group g covers sr in [5g, 5g+5),
// i2 = g/5, dr0 = (g%5)*5. Each block fills k-run [dr0*48, dr0*48+240) of the
// 64 A-rows m = (b*16+i2)*64 + j2.
__global__ void __launch_bounds__(256) k_sample(
    const float* __restrict__ x, const float* __restrict__ dist) {
    extern __shared__ float sm[];
    float* s_img = sm;              // 3*5*1024
    float* s_cos = sm + 15360;      // 1024
    float* s_sin = s_cos + 1024;    // 1024

    const int b = blockIdx.y;
    const int g = blockIdx.x;       // 0..79
    const int tid = threadIdx.x;
    const float PI = 3.14159265358979323846f;

    for (int ia = tid; ia < NA; ia += 256) {
        float phi = 2.0f * PI * (ia + 0.5f) * (1.0f / (float)NA);
        float sv, cv; sincosf(phi, &sv, &cv);
        s_cos[ia] = cv; s_sin[ia] = sv;
    }
    const float c0 = 0.2f + dist[b * 4 + 0];
    const float c1 = 0.2f + dist[b * 4 + 1];
    const float c2 = 0.2f + dist[b * 4 + 2];
    const float c3 = 0.2f + dist[b * 4 + 3];
    const float tmax = PI * 0.5f, tm2 = tmax * tmax;
    const float ptm = tmax * (c0 + tm2 * (c1 + tm2 * (c2 + tm2 * c3)));
    float rrow[5];
#pragma unroll
    for (int rr = 0; rr < 5; rr++) {
        float th = tmax * ((float)(g * 5 + rr) + 0.5f) * (1.0f / 400.0f);
        float t2 = th * th;
        float pt = th * (c0 + t2 * (c1 + t2 * (c2 + t2 * c3)));
        rrow[rr] = pt / ptm * 112.0f;
    }
    __syncthreads();

    const float* xb = x + (size_t)b * (3 * 224 * 224);
    for (int idx = tid; idx < 5 * NA; idx += 256) {
        int rr = idx >> 10, ia = idx & 1023;
        float r = rrow[rr];
        float xc = r * s_cos[ia], yc = r * s_sin[ia];
        float gx = (yc / 112.0f + 1.0f) * 0.5f * 223.0f;
        float gy = (xc / 112.0f + 1.0f) * 0.5f * 223.0f;
        float fx0 = floorf(gx), fy0 = floorf(gy);
        float wx1 = gx - fx0, wx0 = 1.0f - wx1;
        float wy1 = gy - fy0, wy0 = 1.0f - wy1;
        int ix0 = (int)fx0, iy0 = (int)fy0, ix1 = ix0 + 1, iy1 = iy0 + 1;
        float vx0 = (ix0 >= 0 && ix0 <= 223) ? 1.f : 0.f;
        float vx1 = (ix1 >= 0 && ix1 <= 223) ? 1.f : 0.f;
        float vy0 = (iy0 >= 0 && iy0 <= 223) ? 1.f : 0.f;
        float vy1 = (iy1 >= 0 && iy1 <= 223) ? 1.f : 0.f;
        int cx0 = min(max(ix0, 0), 223), cx1 = min(max(ix1, 0), 223);
        int cy0 = min(max(iy0, 0), 223), cy1 = min(max(iy1, 0), 223);
        float w00 = wx0 * wy0 * vx0 * vy0, w10 = wx1 * wy0 * vx1 * vy0;
        float w01 = wx0 * wy1 * vx0 * vy1, w11 = wx1 * wy1 * vx1 * vy1;
        int i00 = cy0 * 224 + cx0, i10 = cy0 * 224 + cx1;
        int i01 = cy1 * 224 + cx0, i11 = cy1 * 224 + cx1;
#pragma unroll
        for (int cch = 0; cch < 3; cch++) {
            const float* p = xb + cch * (224 * 224);
            s_img[(cch * 5 + rr) * NA + ia] =
                w00 * p[i00] + w10 * p[i10] + w01 * p[i01] + w11 * p[i11];
        }
    }
    __syncthreads();

    // write phase: 64 rows x 240 k-elems = 1920 uint4 (8 elems each) per array
    const int i2 = g / 5, dr0 = (g % 5) * 5;
    const size_t mbase = ((size_t)b * 16 + i2) * 64;
    for (int q = tid; q < 1920; q += 256) {
        const int row = q / 30, u = q % 30;
        const int e0 = u * 8;
        const int rr = e0 / 48, rem = e0 % 48;
        const int c = rem >> 4, da0 = rem & 15;   // da0 in {0, 8}
        const float* src = &s_img[(c * 5 + rr) * NA + row * 16 + da0];
        float4 f0 = *(const float4*)src;
        float4 f1 = *(const float4*)(src + 4);
        uint32_t hu[4], lu[4];
        __nv_bfloat16 h0, l0, h1, l1;
        split_hl(f0.x, h0, l0); split_hl(f0.y, h1, l1); hu[0] = pack_bf2(h0, h1); lu[0] = pack_bf2(l0, l1);
        split_hl(f0.z, h0, l0); split_hl(f0.w, h1, l1); hu[1] = pack_bf2(h0, h1); lu[1] = pack_bf2(l0, l1);
        split_hl(f1.x, h0, l0); split_hl(f1.y, h1, l1); hu[2] = pack_bf2(h0, h1); lu[2] = pack_bf2(l0, l1);
        split_hl(f1.z, h0, l0); split_hl(f1.w, h1, l1); hu[3] = pack_bf2(h0, h1); lu[3] = pack_bf2(l0, l1);
        const size_t koff = (size_t)(mbase + row) * KPAD + (dr0 + rr) * 48 + rem;
        *(uint4*)(g_Ah + koff) = *(uint4*)hu;
        *(uint4*)(g_Al + koff) = *(uint4*)lu;
    }
}

// ---------------- GEMM: M-tile 64, N=96, K=1216 (19 chunks of 64) -----------
// smem per stage: Ah 64*144 | Al | Bh 96*144 | Bl
static constexpr int STG = 46080;
static constexpr int SMEM_GEMM = 2 * STG + 512;

__device__ __forceinline__ void stage_copy(
    uint32_t smb, int s,
    const __nv_bfloat16* __restrict__ Ah, const __nv_bfloat16* __restrict__ Al,
    const __nv_bfloat16* __restrict__ Bh, const __nv_bfloat16* __restrict__ Bl,
    size_t m0, int kc, int tid) {
    const uint32_t base = smb + s * STG;
    const size_t koff = (size_t)kc * 64;
#pragma unroll
    for (int k = 0; k < 4; k++) {          // A: 1024 x 16B
        int i = tid + k * 256;
        const __nv_bfloat16* src = (i & 512) ? Al : Ah;
        int rr = (i >> 3) & 63, c = i & 7;
        cp16(base + (i >> 9) * 9216 + rr * 144 + c * 16,
             src + (m0 + rr) * (size_t)KPAD + koff + c * 8);
    }
#pragma unroll
    for (int k = 0; k < 6; k++) {          // B: 1536 x 16B
        int i = tid + k * 256;
        int arr = (i >= 768) ? 1 : 0;
        int jj = i - arr * 768;
        const __nv_bfloat16* src = arr ? Bl : Bh;
        int rr = jj >> 3, c = jj & 7;
        cp16(base + 18432 + arr * 13824 + rr * 144 + c * 16,
             src + (size_t)rr * KPAD + koff + c * 8);
    }
    cp_commit();
}

__global__ void __launch_bounds__(256) k_gemm(
    const __nv_bfloat16* __restrict__ Ah, const __nv_bfloat16* __restrict__ Al,
    const __nv_bfloat16* __restrict__ Bh, const __nv_bfloat16* __restrict__ Bl,
    const float* __restrict__ bias, float* __restrict__ outp) {
    extern __shared__ char smc[];
    const uint32_t smb = smem_u32(smc);
    float* s_bias = (float*)(smc + 2 * STG);
    const int tid = threadIdx.x, w = tid >> 5, l = tid & 31;
    if (tid < 96) s_bias[tid] = bias[tid];

    const int warp_m = w & 1, warp_n = w >> 1;        // 2 x 4 warps
    const int mbase = warp_m * 32, nbase = warp_n * 24;
    const size_t m0 = (size_t)blockIdx.x * 64;
    const int nch = KPAD / 64;                        // 19

    const int t8 = l >> 3, lr = l & 7;
    const int a_r = (t8 & 1) * 8 + lr, a_c = (t8 >> 1) * 16;
    const int b_r = (t8 >> 1) * 8 + lr, b_c = (t8 & 1) * 16;
    const int b2_r = 16 + lr, b2_c = (t8 & 1) * 16;

    float acc[2][3][4];
#pragma unroll
    for (int mf = 0; mf < 2; mf++)
#pragma unroll
        for (int nt = 0; nt < 3; nt++)
#pragma unroll
            for (int i = 0; i < 4; i++) acc[mf][nt][i] = 0.f;

    stage_copy(smb, 0, Ah, Al, Bh, Bl, m0, 0, tid);

    for (int kc = 0; kc < nch; kc++) {
        if (kc + 1 < nch) {
            stage_copy(smb, (kc + 1) & 1, Ah, Al, Bh, Bl, m0, kc + 1, tid);
            cp_wait<1>();
        } else {
            cp_wait<0>();
        }
        __syncthreads();

        const uint32_t sA = smb + (kc & 1) * STG;
        const uint32_t aAh = sA + (mbase + a_r) * 144 + a_c;
        const uint32_t aAl = aAh + 9216;
        const uint32_t sB = sA + 18432;
        const uint32_t aBh = sB + (nbase + b_r) * 144 + b_c;
        const uint32_t aBl = aBh + 13824;
        const uint32_t aBh2 = sB + (nbase + b2_r) * 144 + b2_c;
        const uint32_t aBl2 = aBh2 + 13824;

#pragma unroll
        for (int ks = 0; ks < 4; ks++) {
            const int kb = ks * 32;
            uint32_t ah[2][4], al[2][4], bh[3][2], bl[3][2];
            LDSM_X4(ah[0][0], ah[0][1], ah[0][2], ah[0][3], aAh + kb);
            LDSM_X4(ah[1][0], ah[1][1], ah[1][2], ah[1][3], aAh + 2304 + kb);
            LDSM_X4(al[0][0], al[0][1], al[0][2], al[0][3], aAl + kb);
            LDSM_X4(al[1][0], al[1][1], al[1][2], al[1][3], aAl + 2304 + kb);
            LDSM_X4(bh[0][0], bh[0][1], bh[1][0], bh[1][1], aBh + kb);
            LDSM_X2(bh[2][0], bh[2][1], aBh2 + kb);
            LDSM_X4(bl[0][0], bl[0][1], bl[1][0], bl[1][1], aBl + kb);
            LDSM_X2(bl[2][0], bl[2][1], aBl2 + kb);
#pragma unroll
            for (int mf = 0; mf < 2; mf++)
#pragma unroll
                for (int nt = 0; nt < 3; nt++) {
                    MMA_BF16(acc[mf][nt], ah[mf][0], ah[mf][1], ah[mf][2], ah[mf][3],
                             bh[nt][0], bh[nt][1]);
                    MMA_BF16(acc[mf][nt], ah[mf][0], ah[mf][1], ah[mf][2], ah[mf][3],
                             bl[nt][0], bl[nt][1]);
                    MMA_BF16(acc[mf][nt], al[mf][0], al[mf][1], al[mf][2], al[mf][3],
                             bh[nt][0], bh[nt][1]);
                }
        }
        __syncthreads();
    }

#pragma unroll
    for (int mf = 0; mf < 2; mf++)
#pragma unroll
        for (int half = 0; half < 2; half++) {
            const size_t m = m0 + mbase + mf * 16 + (l >> 2) + half * 8;
            float* dst = outp + m * 96;
#pragma unroll
            for (int nt = 0; nt < 3; nt++) {
                const int n = nbase + nt * 8 + (l & 3) * 2;
                float2 v;
                v.x = acc[mf][nt][half * 2 + 0] + s_bias[n];
                v.y = acc[mf][nt][half * 2 + 1] + s_bias[n + 1];
                *(float2*)(dst + n) = v;
            }
        }
}

extern "C" void kernel_launch(void* const* d_in, const int* in_sizes, int n_in,
                              void* d_out, int out_size) {
    const float* x    = (const float*)d_in[0];
    const float* dist = (const float*)d_in[1];
    const float* w1   = (const float*)d_in[2];
    const float* b1   = (const float*)d_in[3];
    const float* w2   = (const float*)d_in[4];
    const float* b2   = (const float*)d_in[5];
    float* out = (float*)d_out;

    const int sm_sample = (15360 + 2048) * 4;
    cudaFuncSetAttribute(k_sample, cudaFuncAttributeMaxDynamicSharedMemorySize, sm_sample);
    cudaFuncSetAttribute(k_gemm, cudaFuncAttributeMaxDynamicSharedMemorySize, SMEM_GEMM);

    __nv_bfloat16 *Ah, *Al, *Bh, *Bl;
    float* bm;
    cudaGetSymbolAddress((void**)&Ah, g_Ah);
    cudaGetSymbolAddress((void**)&Al, g_Al);
    cudaGetSymbolAddress((void**)&Bh, g_Bh);
    cudaGetSymbolAddress((void**)&Bl, g_Bl);
    cudaGetSymbolAddress((void**)&bm, g_bm);

    const int write_theta = (out_size >= B_SZ * 1024 * EMB + B_SZ) ? 1 : 0;
    k_prep<<<96, 256>>>(w1, b1, w2, b2, out, write_theta);
    k_sample<<<dim3(80, B_SZ), 256, sm_sample>>>(x, dist);
    // single GEMM: M=32768 -> 512 tiles of 64, N=96, K=1216
    k_gemm<<<512, 256, SMEM_GEMM>>>(Ah, Al, Bh, Bl, bm, out);
}

// round 12
// speedup vs baseline: 6.7687x; 1.1822x over previous
#include <cuda_runtime.h>
#include <cuda_bf16.h>
#include <math.h>
#include <stdint.h>

// ---------------------------------------------------------------------------
// PatchEmbed fully fused: polar bilinear sampling + merged-conv GEMM in ONE
// kernel. out[m][o2] = sum_k A[m][k] * Wm[o2][k] + bm[o2],
//   m=(b*16+i2)*64+j2, k=dr*48+c*16+da, K=1200 (25 chunks of 48).
// Each CTA = one m-tile (b,i2); K-chunk dr needs exactly one sampled polar
// row (3ch x 1024 az) -> sampled on the fly into smem stage (hi/lo bf16).
// Precision: D = Ah*Bh + Ah*Bl + Al*Bh (fp32 acc).
// ---------------------------------------------------------------------------

#define B_SZ 32
#define EMB  96
#define NA   1024
#define KTOT 1200

static __device__ __align__(256) __nv_bfloat16 g_Bh[96 * KTOT];
static __device__ __align__(256) __nv_bfloat16 g_Bl[96 * KTOT];
static __device__ float g_bm[96];

__device__ __forceinline__ uint32_t pack_bf2(__nv_bfloat16 a, __nv_bfloat16 b) {
    return (uint32_t)__bfloat16_as_ushort(a) | ((uint32_t)__bfloat16_as_ushort(b) << 16);
}
__device__ __forceinline__ void split_hl(float v, __nv_bfloat16& h, __nv_bfloat16& l) {
    h = __float2bfloat16(v);
    l = __float2bfloat16(v - __bfloat162float(h));
}
__device__ __forceinline__ uint32_t smem_u32(const void* p) {
    uint32_t a;
    asm("{ .reg .u64 t; cvta.to.shared.u64 t, %1; cvt.u32.u64 %0, t; }" : "=r"(a) : "l"(p));
    return a;
}
__device__ __forceinline__ void cp16(uint32_t dst, const void* src) {
    asm volatile("cp.async.cg.shared.global [%0], [%1], 16;" :: "r"(dst), "l"(src) : "memory");
}
template <int N> __device__ __forceinline__ void cp_wait() {
    asm volatile("cp.async.wait_group %0;" :: "n"(N) : "memory");
}
__device__ __forceinline__ void cp_commit() {
    asm volatile("cp.async.commit_group;" ::: "memory");
}
#define LDSM_X4(r0, r1, r2, r3, a) \
    asm volatile("ldmatrix.sync.aligned.m8n8.x4.shared.b16 {%0,%1,%2,%3}, [%4];" \
                 : "=r"(r0), "=r"(r1), "=r"(r2), "=r"(r3) : "r"(a))
#define LDSM_X2(r0, r1, a) \
    asm volatile("ldmatrix.sync.aligned.m8n8.x2.shared.b16 {%0,%1}, [%2];" \
                 : "=r"(r0), "=r"(r1) : "r"(a))
#define MMA_BF16(c, a0, a1, a2, a3, b0, b1) \
    asm volatile("mma.sync.aligned.m16n8k16.row.col.f32.bf16.bf16.f32 " \
                 "{%0,%1,%2,%3}, {%4,%5,%6,%7}, {%8,%9}, {%0,%1,%2,%3};" \
                 : "+f"((c)[0]), "+f"((c)[1]), "+f"((c)[2]), "+f"((c)[3]) \
                 : "r"(a0), "r"(a1), "r"(a2), "r"(a3), "r"(b0), "r"(b1))

// ---------------- prep: merge conv weights, hi/lo split; bias; theta --------
__global__ void __launch_bounds__(256) k_prep(
    const float* __restrict__ w1, const float* __restrict__ b1,
    const float* __restrict__ w2, const float* __restrict__ b2,
    float* __restrict__ out, int write_theta) {
    __shared__ float s_w1[96 * 60];
    __shared__ float s_w2[96 * 20];
    const int o2 = blockIdx.x;
    const int tid = threadIdx.x;
    for (int i = tid; i < 96 * 60; i += 256) s_w1[i] = w1[i];
    for (int i = tid; i < 96 * 20; i += 256) s_w2[i] = w2[o2 * (96 * 20) + i];
    __syncthreads();

    for (int k = tid; k < KTOT; k += 256) {
        int dr = k / 48, rem = k % 48;
        int c = rem >> 4, da = rem & 15;
        int kr = dr / 5, r5 = dr % 5;
        int ka = da >> 2, a4 = da & 3;
        int w2i = kr * 4 + ka;
        int w1i = c * 20 + r5 * 4 + a4;
        float acc = 0.f;
#pragma unroll 4
        for (int o1 = 0; o1 < 96; o1++)
            acc += s_w2[o1 * 20 + w2i] * s_w1[o1 * 60 + w1i];
        __nv_bfloat16 h, l; split_hl(acc, h, l);
        g_Bh[o2 * KTOT + k] = h;
        g_Bl[o2 * KTOT + k] = l;
    }
    if (tid == 0) {
        float bm = b2[o2];
        for (int o1 = 0; o1 < 96; o1++) {
            float s = 0.f;
            for (int t = 0; t < 20; t++) s += s_w2[o1 * 20 + t];
            bm += s * b1[o1];
        }
        g_bm[o2] = bm;
    }
    if (write_theta && o2 == 0 && tid < B_SZ)
        out[(size_t)B_SZ * 1024 * EMB + tid] = 1.57079632679489662f;
}

// ---------------- fused sample + GEMM ----------------------------------------
// stage layout (bytes from stage base, row stride 112B = 56 bf16):
//   Ah 0 (64x112) | Al 7168 | Bh 14336 (96x112) | Bl 25088    STG=35840
static constexpr int STG = 35840;
static constexpr int OFF_AL = 7168, OFF_BH = 14336, OFF_BL = 25088;
static constexpr int OFF_COS = 2 * STG;             // 4096 B
static constexpr int OFF_SIN = OFF_COS + 4096;      // 4096 B
static constexpr int OFF_BIAS = OFF_SIN + 4096;     // 384 B
static constexpr int SMEM_MAIN = OFF_BIAS + 384;    // 80,256 B

__global__ void __launch_bounds__(256, 2) k_main(
    const float* __restrict__ x, const float* __restrict__ dist,
    const __nv_bfloat16* __restrict__ Bh, const __nv_bfloat16* __restrict__ Bl,
    const float* __restrict__ bias, float* __restrict__ outp) {
    extern __shared__ char smc[];
    const uint32_t smb = smem_u32(smc);
    float* s_cos = (float*)(smc + OFF_COS);
    float* s_sin = (float*)(smc + OFF_SIN);
    float* s_bias = (float*)(smc + OFF_BIAS);

    const int tid = threadIdx.x, w = tid >> 5, l = tid & 31;
    const int b = blockIdx.x >> 4;
    const int i2 = blockIdx.x & 15;
    const float PI = 3.14159265358979323846f;

    // prologue: sincos table + bias + distortion coeffs
    for (int ia = tid; ia < NA; ia += 256) {
        float phi = 2.0f * PI * (ia + 0.5f) * (1.0f / (float)NA);
        float sv, cv; sincosf(phi, &sv, &cv);
        s_cos[ia] = cv; s_sin[ia] = sv;
    }
    if (tid < 96) s_bias[tid] = bias[tid];
    const float c0 = 0.2f + dist[b * 4 + 0];
    const float c1 = 0.2f + dist[b * 4 + 1];
    const float c2 = 0.2f + dist[b * 4 + 2];
    const float c3 = 0.2f + dist[b * 4 + 3];
    const float tmax = PI * 0.5f, tm2 = tmax * tmax;
    const float ptm = tmax * (c0 + tm2 * (c1 + tm2 * (c2 + tm2 * c3)));
    const float* xb = x + (size_t)b * (3 * 224 * 224);
    __syncthreads();

    // fill stage s with chunk dr: sample A row + cp.async B chunk
    auto fill = [&](int s, int dr) {
        const uint32_t base = smb + s * STG;
        // radius for sampled row sr = i2*25+dr
        float th = tmax * ((float)(i2 * 25 + dr) + 0.5f) * (1.0f / 400.0f);
        float t2 = th * th;
        float r = th * (c0 + t2 * (c1 + t2 * (c2 + t2 * c3))) / ptm * 112.0f;
#pragma unroll
        for (int t = 0; t < 12; t++) {                 // 3072 samples
            int idx = tid + t * 256;
            int c = idx >> 10, ia = idx & 1023;
            float xc = r * s_cos[ia], yc = r * s_sin[ia];
            float gx = (yc / 112.0f + 1.0f) * 0.5f * 223.0f;
            float gy = (xc / 112.0f + 1.0f) * 0.5f * 223.0f;
            float fx0 = floorf(gx), fy0 = floorf(gy);
            float wx1 = gx - fx0, wx0 = 1.0f - wx1;
            float wy1 = gy - fy0, wy0 = 1.0f - wy1;
            int ix0 = (int)fx0, iy0 = (int)fy0, ix1 = ix0 + 1, iy1 = iy0 + 1;
            float vx0 = (ix0 >= 0 && ix0 <= 223) ? 1.f : 0.f;
            float vx1 = (ix1 >= 0 && ix1 <= 223) ? 1.f : 0.f;
            float vy0 = (iy0 >= 0 && iy0 <= 223) ? 1.f : 0.f;
            float vy1 = (iy1 >= 0 && iy1 <= 223) ? 1.f : 0.f;
            int cx0 = min(max(ix0, 0), 223), cx1 = min(max(ix1, 0), 223);
            int cy0 = min(max(iy0, 0), 223), cy1 = min(max(iy1, 0), 223);
            float w00 = wx0 * wy0 * vx0 * vy0, w10 = wx1 * wy0 * vx1 * vy0;
            float w01 = wx0 * wy1 * vx0 * vy1, w11 = wx1 * wy1 * vx1 * vy1;
            const float* p = xb + c * (224 * 224);
            int i00 = cy0 * 224 + cx0, i10 = cy0 * 224 + cx1;
            int i01 = cy1 * 224 + cx0, i11 = cy1 * 224 + cx1;
            float v = w00 * p[i00] + w10 * p[i10] + w01 * p[i01] + w11 * p[i11];
            __nv_bfloat16 h, lo; split_hl(v, h, lo);
            // A[row=j2][klocal = c*16+da], j2 = ia>>4, da = ia&15
            uint32_t off = (uint32_t)(ia >> 4) * 112 + (uint32_t)(c * 16 + (ia & 15)) * 2;
            *(__nv_bfloat16*)(smc + s * STG + off) = h;
            *(__nv_bfloat16*)(smc + s * STG + OFF_AL + off) = lo;
        }
        // B chunk: 96 rows x 48 elems, hi+lo = 1152 x 16B
        const size_t koff = (size_t)dr * 48;
#pragma unroll
        for (int t = 0; t < 5; t++) {
            int i = tid + t * 256;
            if (i < 1152) {
                int arr = i >= 576;
                int j = i - arr * 576;
                int row = j / 6, col = j % 6;
                const __nv_bfloat16* src = arr ? Bl : Bh;
                cp16(base + (arr ? OFF_BL : OFF_BH) + row * 112 + col * 16,
                     src + (size_t)row * KTOT + koff + col * 8);
            }
        }
        cp_commit();
    };

    const int warp_m = w & 1, warp_n = w >> 1;        // 2 x 4 warps
    const int mbase = warp_m * 32, nbase = warp_n * 24;
    const int t8 = l >> 3, lr = l & 7;
    const int a_r = (t8 & 1) * 8 + lr, a_c = (t8 >> 1) * 16;
    const int b_r = (t8 >> 1) * 8 + lr, b_c = (t8 & 1) * 16;
    const int b2_r = 16 + lr, b2_c = (t8 & 1) * 16;

    float acc[2][3][4];
#pragma unroll
    for (int mf = 0; mf < 2; mf++)
#pragma unroll
        for (int nt = 0; nt < 3; nt++)
#pragma unroll
            for (int i = 0; i < 4; i++) acc[mf][nt][i] = 0.f;

    fill(0, 0);

    for (int dr = 0; dr < 25; dr++) {
        const int q = dr & 1;
        if (dr + 1 < 25) { fill(q ^ 1, dr + 1); cp_wait<1>(); }
        else             { cp_wait<0>(); }
        __syncthreads();

        const uint32_t sA = smb + q * STG;
        const uint32_t aAh = sA + (mbase + a_r) * 112 + a_c;
        const uint32_t aAl = aAh + OFF_AL;
        const uint32_t aBh = sA + OFF_BH + (nbase + b_r) * 112 + b_c;
        const uint32_t aBl = aBh + (OFF_BL - OFF_BH);
        const uint32_t aBh2 = sA + OFF_BH + (nbase + b2_r) * 112 + b2_c;
        const uint32_t aBl2 = aBh2 + (OFF_BL - OFF_BH);

#pragma unroll
        for (int ks = 0; ks < 3; ks++) {
            const int kb = ks * 32;
            uint32_t ah[2][4], al[2][4], bh[3][2], bl[3][2];
            LDSM_X4(ah[0][0], ah[0][1], ah[0][2], ah[0][3], aAh + kb);
            LDSM_X4(ah[1][0], ah[1][1], ah[1][2], ah[1][3], aAh + 16 * 112 + kb);
            LDSM_X4(al[0][0], al[0][1], al[0][2], al[0][3], aAl + kb);
            LDSM_X4(al[1][0], al[1][1], al[1][2], al[1][3], aAl + 16 * 112 + kb);
            LDSM_X4(bh[0][0], bh[0][1], bh[1][0], bh[1][1], aBh + kb);
            LDSM_X2(bh[2][0], bh[2][1], aBh2 + kb);
            LDSM_X4(bl[0][0], bl[0][1], bl[1][0], bl[1][1], aBl + kb);
            LDSM_X2(bl[2][0], bl[2][1], aBl2 + kb);
#pragma unroll
            for (int mf = 0; mf < 2; mf++)
#pragma unroll
                for (int nt = 0; nt < 3; nt++) {
                    MMA_BF16(acc[mf][nt], ah[mf][0], ah[mf][1], ah[mf][2], ah[mf][3],
                             bh[nt][0], bh[nt][1]);
                    MMA_BF16(acc[mf][nt], ah[mf][0], ah[mf][1], ah[mf][2], ah[mf][3],
                             bl[nt][0], bl[nt][1]);
                    MMA_BF16(acc[mf][nt], al[mf][0], al[mf][1], al[mf][2], al[mf][3],
                             bh[nt][0], bh[nt][1]);
                }
        }
        __syncthreads();
    }

    // epilogue: out[b][i2*64+j2][o2]
    const size_t m0 = (size_t)blockIdx.x * 64;
#pragma unroll
    for (int mf = 0; mf < 2; mf++)
#pragma unroll
        for (int half = 0; half < 2; half++) {
            const size_t m = m0 + mbase + mf * 16 + (l >> 2) + half * 8;
            float* dst = outp + m * 96;
#pragma unroll
            for (int nt = 0; nt < 3; nt++) {
                const int n = nbase + nt * 8 + (l & 3) * 2;
                float2 v;
                v.x = acc[mf][nt][half * 2 + 0] + s_bias[n];
                v.y = acc[mf][nt][half * 2 + 1] + s_bias[n + 1];
                *(float2*)(dst + n) = v;
            }
        }
}

extern "C" void kernel_launch(void* const* d_in, const int* in_sizes, int n_in,
                              void* d_out, int out_size) {
    const float* x    = (const float*)d_in[0];
    const float* dist = (const float*)d_in[1];
    const float* w1   = (const float*)d_in[2];
    const float* b1   = (const float*)d_in[3];
    const float* w2   = (const float*)d_in[4];
    const float* b2   = (const float*)d_in[5];
    float* out = (float*)d_out;

    cudaFuncSetAttribute(k_main, cudaFuncAttributeMaxDynamicSharedMemorySize, SMEM_MAIN);

    __nv_bfloat16 *Bh, *Bl;
    float* bm;
    cudaGetSymbolAddress((void**)&Bh, g_Bh);
    cudaGetSymbolAddress((void**)&Bl, g_Bl);
    cudaGetSymbolAddress((void**)&bm, g_bm);

    const int write_theta = (out_size >= B_SZ * 1024 * EMB + B_SZ) ? 1 : 0;
    k_prep<<<96, 256>>>(w1, b1, w2, b2, out, write_theta);
    k_main<<<512, 256, SMEM_MAIN>>>(x, dist, Bh, Bl, bm, out);
}